// round 1
// baseline (speedup 1.0000x reference)
#include <cuda_runtime.h>
#include <math.h>

#define DMODEL 1024
#define NHEADS 16
#define HDIM   64
#define BATCH  2
#define SEQ    2048
#define NQT    (SEQ / 64)   // 32 q/k tiles

// ---------------- scratch (no allocations allowed) ----------------
__device__ float g_qp[BATCH * SEQ * DMODEL];
__device__ float g_kp[BATCH * SEQ * DMODEL];
__device__ float g_vp[BATCH * SEQ * DMODEL];
__device__ float g_ctx[BATCH * SEQ * DMODEL];
__device__ float g_rowinv[BATCH * NHEADS * SEQ];

#define LD4(dst, src) do { float4 _t = *(const float4*)(src); \
    (dst)[0]=_t.x; (dst)[1]=_t.y; (dst)[2]=_t.z; (dst)[3]=_t.w; } while(0)

// ================================================================
// SGEMM: C[M,1024] = X[M,1024] @ W[1024,1024]^T + bias
// BM=BN=128, BK=16, 256 threads, 8x8 per-thread (2x4 + 2x4 fragments)
// ================================================================
__global__ __launch_bounds__(256, 2)
void sgemm_wt_kernel(const float* __restrict__ X, const float* __restrict__ W,
                     const float* __restrict__ bias, float* __restrict__ C)
{
    constexpr int K = 1024, N = 1024, BK = 16;
    __shared__ float Xs[BK][128];   // [k][m]
    __shared__ float Ws[BK][128];   // [k][n]

    const int bm = blockIdx.y * 128;
    const int bn = blockIdx.x * 128;
    const int tid  = threadIdx.x;
    const int tcol = tid & 15;
    const int trow = tid >> 4;

    float acc[2][4][2][4];
    #pragma unroll
    for (int ih=0; ih<2; ih++)
      #pragma unroll
      for (int i=0; i<4; i++)
        #pragma unroll
        for (int jh=0; jh<2; jh++)
          #pragma unroll
          for (int j=0; j<4; j++) acc[ih][i][jh][j] = 0.f;

    const int lrow = tid >> 2;        // 0..63
    const int lk   = (tid & 3) * 4;   // 0,4,8,12

    for (int kt = 0; kt < K; kt += BK) {
        #pragma unroll
        for (int u = 0; u < 2; ++u) {
            int r = lrow + u * 64;
            float4 xv = *(const float4*)(X + (size_t)(bm + r) * K + kt + lk);
            Xs[lk+0][r]=xv.x; Xs[lk+1][r]=xv.y; Xs[lk+2][r]=xv.z; Xs[lk+3][r]=xv.w;
            float4 wv = *(const float4*)(W + (size_t)(bn + r) * K + kt + lk);
            Ws[lk+0][r]=wv.x; Ws[lk+1][r]=wv.y; Ws[lk+2][r]=wv.z; Ws[lk+3][r]=wv.w;
        }
        __syncthreads();
        #pragma unroll
        for (int k = 0; k < BK; ++k) {
            float a[2][4], b[2][4];
            LD4(a[0], &Xs[k][trow*4]);
            LD4(a[1], &Xs[k][64 + trow*4]);
            LD4(b[0], &Ws[k][tcol*4]);
            LD4(b[1], &Ws[k][64 + tcol*4]);
            #pragma unroll
            for (int ih=0; ih<2; ih++)
              #pragma unroll
              for (int i=0; i<4; i++)
                #pragma unroll
                for (int jh=0; jh<2; jh++)
                  #pragma unroll
                  for (int j=0; j<4; j++)
                    acc[ih][i][jh][j] += a[ih][i] * b[jh][j];
        }
        __syncthreads();
    }

    #pragma unroll
    for (int ih=0; ih<2; ih++) {
      #pragma unroll
      for (int i=0; i<4; i++) {
        int r = bm + ih*64 + trow*4 + i;
        #pragma unroll
        for (int jh=0; jh<2; jh++) {
            int c = bn + jh*64 + tcol*4;
            float4 bb = *(const float4*)(bias + c);
            float4 o;
            o.x = acc[ih][i][jh][0] + bb.x;
            o.y = acc[ih][i][jh][1] + bb.y;
            o.z = acc[ih][i][jh][2] + bb.z;
            o.w = acc[ih][i][jh][3] + bb.w;
            *(float4*)(C + (size_t)r * N + c) = o;
        }
      }
    }
}

// ================================================================
// Fused causal attention: per (b,h,q-tile of 64 rows).
// Writes unnormalized exp(scores) to w, accumulates ctx (normalized at end),
// stores 1/rowsum to g_rowinv for the normalize pass over w.
// Dynamic smem layout (floats):
//   Qs [64][64] d-major       @ 0
//   Ks [64][64] d-major       @ 4096
//   Vs [64][68] k-major       @ 8192
//   Ps [64][68] (PsT[c][r])   @ 8192+4352
// total 16896 floats = 67584 bytes
// ================================================================
#define ATTN_SMEM_FLOATS 16896
#define ATTN_SMEM_BYTES  (ATTN_SMEM_FLOATS * 4)

__global__ __launch_bounds__(256, 2)
void attn_kernel(const float* __restrict__ qp, const float* __restrict__ kp,
                 const float* __restrict__ vp, float* __restrict__ w,
                 float* __restrict__ ctx, float* __restrict__ rowinv)
{
    extern __shared__ float sm[];
    float* Qs = sm;                 // [d][r]  pitch 64
    float* Ks = sm + 4096;          // [d][c]  pitch 64
    float* Vs = sm + 8192;          // [k][n]  pitch 68
    float* Ps = sm + 8192 + 64*68;  // [c][r]  pitch 68

    const int qt = (int)gridDim.x - 1 - (int)blockIdx.x;  // big tiles first
    const int h  = blockIdx.y;
    const int b  = blockIdx.z;
    const int q0 = qt * 64;
    const int tid  = threadIdx.x;
    const int tcol = tid & 15;
    const int trow = tid >> 4;
    const float scale = 0.125f;  // 1/sqrt(64)

    // load Q tile, transposed into Qs[d][r]
    {
        int r  = tid >> 2;
        int dq = (tid & 3) * 16;
        const float* src = qp + ((size_t)(b*SEQ + q0 + r)) * DMODEL + h*HDIM + dq;
        #pragma unroll
        for (int u = 0; u < 4; ++u) {
            float4 v = *(const float4*)(src + u*4);
            int d = dq + u*4;
            Qs[(d+0)*64 + r] = v.x; Qs[(d+1)*64 + r] = v.y;
            Qs[(d+2)*64 + r] = v.z; Qs[(d+3)*64 + r] = v.w;
        }
    }

    float ctxacc[4][4];
    #pragma unroll
    for (int i=0;i<4;i++)
      #pragma unroll
      for (int j=0;j<4;j++) ctxacc[i][j]=0.f;
    float rsum[4] = {0.f, 0.f, 0.f, 0.f};

    float* wbase = w + ((size_t)((b*NHEADS + h)*SEQ)) * SEQ;

    for (int kt = 0; kt <= qt; ++kt) {
        const int k0 = kt * 64;
        __syncthreads();   // prev GEMM2 reads of Vs/Ps done before overwrite
        {
            int r  = tid >> 2;
            int dq = (tid & 3) * 16;
            const float* ksrc = kp + ((size_t)(b*SEQ + k0 + r)) * DMODEL + h*HDIM + dq;
            const float* vsrc = vp + ((size_t)(b*SEQ + k0 + r)) * DMODEL + h*HDIM + dq;
            #pragma unroll
            for (int u = 0; u < 4; ++u) {
                float4 v = *(const float4*)(ksrc + u*4);
                int d = dq + u*4;
                Ks[(d+0)*64 + r] = v.x; Ks[(d+1)*64 + r] = v.y;
                Ks[(d+2)*64 + r] = v.z; Ks[(d+3)*64 + r] = v.w;
                *(float4*)&Vs[r*68 + dq + u*4] = *(const float4*)(vsrc + u*4);
            }
        }
        __syncthreads();

        // GEMM1: S = Q K^T  (4x4 frag per thread)
        float s[4][4];
        #pragma unroll
        for (int i=0;i<4;i++)
          #pragma unroll
          for (int j=0;j<4;j++) s[i][j]=0.f;
        #pragma unroll 16
        for (int d = 0; d < 64; ++d) {
            float a[4], bq[4];
            LD4(a,  &Qs[d*64 + trow*4]);
            LD4(bq, &Ks[d*64 + tcol*4]);
            #pragma unroll
            for (int i=0;i<4;i++)
              #pragma unroll
              for (int j=0;j<4;j++)
                s[i][j] += a[i] * bq[j];
        }

        // exp (unnormalized), mask diag tile, write w, accumulate row sums
        float e[4][4];
        #pragma unroll
        for (int i = 0; i < 4; ++i) {
            int rq = q0 + trow*4 + i;
            #pragma unroll
            for (int j = 0; j < 4; ++j) {
                int ck = k0 + tcol*4 + j;
                float ev = __expf(s[i][j] * scale);
                ev = (ck <= rq) ? ev : 0.f;
                e[i][j] = ev;
                rsum[i] += ev;
            }
            float4 wv = make_float4(e[i][0], e[i][1], e[i][2], e[i][3]);
            *(float4*)(wbase + (size_t)rq * SEQ + k0 + tcol*4) = wv;
        }

        // transpose e into Ps[c][r] (j-permuted to spread banks)
        #pragma unroll
        for (int jj = 0; jj < 4; ++jj) {
            int j = (tcol + jj) & 3;
            int c = tcol*4 + j;
            *(float4*)&Ps[c*68 + trow*4] =
                make_float4(e[0][j], e[1][j], e[2][j], e[3][j]);
        }
        __syncthreads();

        // GEMM2: ctx += P V
        #pragma unroll 16
        for (int k = 0; k < 64; ++k) {
            float a[4], bv[4];
            LD4(a,  &Ps[k*68 + trow*4]);
            LD4(bv, &Vs[k*68 + tcol*4]);
            #pragma unroll
            for (int i=0;i<4;i++)
              #pragma unroll
              for (int j=0;j<4;j++)
                ctxacc[i][j] += a[i] * bv[j];
        }
    }

    // zero-fill masked tiles of w (d_out is poisoned)
    for (int kt = qt + 1; kt < NQT; ++kt) {
        int k0 = kt * 64;
        #pragma unroll
        for (int i = 0; i < 4; ++i) {
            int rq = q0 + trow*4 + i;
            *(float4*)(wbase + (size_t)rq * SEQ + k0 + tcol*4) =
                make_float4(0.f, 0.f, 0.f, 0.f);
        }
    }

    // reduce row sums across the 16 thread-columns (reuse Ks), invert
    __syncthreads();
    float* red   = Ks;   // 64*16 floats
    float* invsm = Vs;   // 64 floats
    #pragma unroll
    for (int i = 0; i < 4; ++i) red[(trow*4 + i)*16 + tcol] = rsum[i];
    __syncthreads();
    if (tid < 64) {
        float t = 0.f;
        #pragma unroll
        for (int u = 0; u < 16; ++u) t += red[tid*16 + u];
        float iv = 1.0f / t;
        invsm[tid] = iv;
        rowinv[((size_t)(b*NHEADS + h))*SEQ + q0 + tid] = iv;
    }
    __syncthreads();

    // scale ctx by 1/rowsum and store into concat layout [b, s, h*64+d]
    #pragma unroll
    for (int i = 0; i < 4; ++i) {
        int r = trow*4 + i;
        float iv = invsm[r];
        float4 o = make_float4(ctxacc[i][0]*iv, ctxacc[i][1]*iv,
                               ctxacc[i][2]*iv, ctxacc[i][3]*iv);
        *(float4*)(ctx + ((size_t)(b*SEQ + q0 + r)) * DMODEL + h*HDIM + tcol*4) = o;
    }
}

// ================================================================
// Normalize w rows by 1/rowsum (lower triangle only; upper is already 0)
// ================================================================
__global__ __launch_bounds__(256)
void norm_w_kernel(float* __restrict__ w, const float* __restrict__ rowinv)
{
    const int r  = blockIdx.x;
    const int bh = blockIdx.y;
    const float iv = rowinv[(size_t)bh * SEQ + r];
    float* row = w + ((size_t)bh * SEQ + r) * SEQ;
    // round valid cols up to the 64-tile boundary (those extras are zeros)
    const int nvec = ((r / 64 + 1) * 64) >> 2;   // float4 count
    for (int i = threadIdx.x; i < nvec; i += blockDim.x) {
        float4 v = *(float4*)(row + i*4);
        v.x *= iv; v.y *= iv; v.z *= iv; v.w *= iv;
        *(float4*)(row + i*4) = v;
    }
}

// ================================================================
// launch
// ================================================================
extern "C" void kernel_launch(void* const* d_in, const int* in_sizes, int n_in,
                              void* d_out, int out_size)
{
    const float* query = (const float*)d_in[0];
    const float* key   = (const float*)d_in[1];
    const float* value = (const float*)d_in[2];
    // d_in[3] = mask (causal, known analytically — unused)
    const float* Wk = (const float*)d_in[4];
    const float* bk = (const float*)d_in[5];
    const float* Wv = (const float*)d_in[6];
    const float* bv = (const float*)d_in[7];
    const float* Wo = (const float*)d_in[8];
    const float* bo = (const float*)d_in[9];

    float* out = (float*)d_out;                               // [2,2048,1024]
    float* w   = out + (size_t)BATCH * SEQ * DMODEL;          // [2,16,2048,2048]

    float* qp  = nullptr; cudaGetSymbolAddress((void**)&qp,  g_qp);
    float* kp  = nullptr; cudaGetSymbolAddress((void**)&kp,  g_kp);
    float* vp  = nullptr; cudaGetSymbolAddress((void**)&vp,  g_vp);
    float* ctx = nullptr; cudaGetSymbolAddress((void**)&ctx, g_ctx);
    float* riv = nullptr; cudaGetSymbolAddress((void**)&riv, g_rowinv);

    cudaFuncSetAttribute(attn_kernel,
                         cudaFuncAttributeMaxDynamicSharedMemorySize,
                         ATTN_SMEM_BYTES);

    dim3 ggrid(DMODEL / 128, (BATCH * SEQ) / 128);   // (8, 32)
    // projections (reference bug preserved: q projected with Wk)
    sgemm_wt_kernel<<<ggrid, 256>>>(query, Wk, bk, qp);
    sgemm_wt_kernel<<<ggrid, 256>>>(key,   Wk, bk, kp);
    sgemm_wt_kernel<<<ggrid, 256>>>(value, Wv, bv, vp);

    attn_kernel<<<dim3(NQT, NHEADS, BATCH), 256, ATTN_SMEM_BYTES>>>(
        qp, kp, vp, w, ctx, riv);

    norm_w_kernel<<<dim3(SEQ, BATCH * NHEADS), 256>>>(w, riv);

    sgemm_wt_kernel<<<ggrid, 256>>>(ctx, Wo, bo, out);
}

// round 2
// speedup vs baseline: 1.9907x; 1.9907x over previous
#include <cuda_runtime.h>
#include <math.h>

#define DMODEL 1024
#define NHEADS 16
#define HDIM   64
#define BATCH  2
#define SEQ    2048
#define NQT    (SEQ / 64)

// ---------------- scratch (no allocations allowed) ----------------
__device__ float g_qp[BATCH * SEQ * DMODEL];
__device__ float g_kp[BATCH * SEQ * DMODEL];
__device__ float g_vp[BATCH * SEQ * DMODEL];
__device__ float g_ctx[BATCH * SEQ * DMODEL];
__device__ float g_rowinv[BATCH * NHEADS * SEQ];

__device__ __forceinline__ unsigned f2tf(float f) {
    unsigned u;
    asm("cvt.rna.tf32.f32 %0, %1;" : "=r"(u) : "f"(f));
    return u;
}

// D += A(16x8) * B(8x8), tf32 inputs, f32 accum
__device__ __forceinline__ void mma8(float* d, const unsigned* a, const unsigned* b) {
    asm volatile(
        "mma.sync.aligned.m16n8k8.row.col.f32.tf32.tf32.f32 "
        "{%0,%1,%2,%3},{%4,%5,%6,%7},{%8,%9},{%0,%1,%2,%3};"
        : "+f"(d[0]), "+f"(d[1]), "+f"(d[2]), "+f"(d[3])
        : "r"(a[0]), "r"(a[1]), "r"(a[2]), "r"(a[3]), "r"(b[0]), "r"(b[1]));
}

// ================================================================
// tf32 GEMM: C[M,1024] = X[M,1024] @ W[1024,1024]^T + bias
// 128x128 tile, BK=32, 256 threads = 8 warps (2x4), warp tile 64x32
// ================================================================
__global__ __launch_bounds__(256, 2)
void gemm_tf32(const float* __restrict__ X, const float* __restrict__ W,
               const float* __restrict__ bias, float* __restrict__ C)
{
    __shared__ unsigned Xs[128][36];   // [m][k], pitch 36 -> bank 4g+t
    __shared__ unsigned Ws[128][36];   // [n][k]

    const int bm = blockIdx.y * 128;
    const int bn = blockIdx.x * 128;
    const int tid = threadIdx.x, lane = tid & 31, wid = tid >> 5;
    const int wm = (wid & 1) * 64, wn = (wid >> 1) * 32;
    const int g = lane >> 2, t = lane & 3;

    float acc[4][4][4];
    #pragma unroll
    for (int mt = 0; mt < 4; mt++)
      #pragma unroll
      for (int nt = 0; nt < 4; nt++)
        #pragma unroll
        for (int i = 0; i < 4; i++) acc[mt][nt][i] = 0.f;

    const int lr = tid >> 1, lk = (tid & 1) * 16;
    const float* xp0 = X + (size_t)(bm + lr) * DMODEL + lk;
    const float* wp0 = W + (size_t)(bn + lr) * DMODEL + lk;

    for (int k0 = 0; k0 < DMODEL; k0 += 32) {
        #pragma unroll
        for (int u = 0; u < 4; ++u) {
            float4 xv = *(const float4*)(xp0 + k0 + u*4);
            Xs[lr][lk+u*4+0] = f2tf(xv.x); Xs[lr][lk+u*4+1] = f2tf(xv.y);
            Xs[lr][lk+u*4+2] = f2tf(xv.z); Xs[lr][lk+u*4+3] = f2tf(xv.w);
            float4 wv = *(const float4*)(wp0 + k0 + u*4);
            Ws[lr][lk+u*4+0] = f2tf(wv.x); Ws[lr][lk+u*4+1] = f2tf(wv.y);
            Ws[lr][lk+u*4+2] = f2tf(wv.z); Ws[lr][lk+u*4+3] = f2tf(wv.w);
        }
        __syncthreads();
        #pragma unroll
        for (int kk = 0; kk < 32; kk += 8) {
            unsigned a[4][4], b[4][2];
            #pragma unroll
            for (int mt = 0; mt < 4; mt++) {
                int row = wm + mt * 16;
                a[mt][0] = Xs[row + g    ][kk + t];
                a[mt][1] = Xs[row + g + 8][kk + t];
                a[mt][2] = Xs[row + g    ][kk + t + 4];
                a[mt][3] = Xs[row + g + 8][kk + t + 4];
            }
            #pragma unroll
            for (int nt = 0; nt < 4; nt++) {
                int col = wn + nt * 8;
                b[nt][0] = Ws[col + g][kk + t];
                b[nt][1] = Ws[col + g][kk + t + 4];
            }
            #pragma unroll
            for (int mt = 0; mt < 4; mt++)
              #pragma unroll
              for (int nt = 0; nt < 4; nt++)
                mma8(acc[mt][nt], a[mt], b[nt]);
        }
        __syncthreads();
    }

    #pragma unroll
    for (int mt = 0; mt < 4; mt++) {
        int r0 = bm + wm + mt * 16 + g;
        #pragma unroll
        for (int nt = 0; nt < 4; nt++) {
            int c = bn + wn + nt * 8 + 2 * t;
            float2 bb = *(const float2*)(bias + c);
            float2 o0 = make_float2(acc[mt][nt][0] + bb.x, acc[mt][nt][1] + bb.y);
            *(float2*)(C + (size_t)r0 * DMODEL + c) = o0;
            float2 o1 = make_float2(acc[mt][nt][2] + bb.x, acc[mt][nt][3] + bb.y);
            *(float2*)(C + (size_t)(r0 + 8) * DMODEL + c) = o1;
        }
    }
}

// ================================================================
// Fused causal attention with tf32 mma.
// Block = (b, h, 64-row q-tile), 256 threads = 8 warps.
// Warp tile on 64x64 score/ctx: wm=(wid&3)*16 rows, wn=(wid>>2)*32 cols.
// smem (words): Qs[64*68] Ks[64*68] Vt[64*68] Ps[64*68] + rsum(64)+inv(64)
// ================================================================
#define ATTN_SMEM_BYTES ((4 * 64 * 68 + 128) * 4)

__global__ __launch_bounds__(256, 2)
void attn_tf32(const float* __restrict__ qp, const float* __restrict__ kp,
               const float* __restrict__ vp, float* __restrict__ w,
               float* __restrict__ ctx, float* __restrict__ rowinv)
{
    extern __shared__ unsigned sm[];
    unsigned* Qs = sm;               // [row][d]   pitch 68
    unsigned* Ks = sm + 64 * 68;     // [key][d]   pitch 68
    unsigned* Vt = sm + 2 * 64 * 68; // [d][key]   pitch 68
    unsigned* Ps = sm + 3 * 64 * 68; // [row][key] pitch 68
    float* rsum_sm = (float*)(sm + 4 * 64 * 68);
    float* invsm   = rsum_sm + 64;

    const int qt = (int)gridDim.x - 1 - (int)blockIdx.x;
    const int h = blockIdx.y, b = blockIdx.z;
    const int q0 = qt * 64;
    const int tid = threadIdx.x, lane = tid & 31, wid = tid >> 5;
    const int wm = (wid & 3) * 16, wn = (wid >> 2) * 32;
    const int g = lane >> 2, t = lane & 3;

    if (tid < 64) rsum_sm[tid] = 0.f;

    // load Q tile [row][d]
    const int lr = tid >> 2, ld = (tid & 3) * 16;
    {
        const float* src = qp + (size_t)(b * SEQ + q0 + lr) * DMODEL + h * HDIM + ld;
        #pragma unroll
        for (int u = 0; u < 4; ++u) {
            float4 v = *(const float4*)(src + u * 4);
            Qs[lr*68 + ld + u*4 + 0] = f2tf(v.x); Qs[lr*68 + ld + u*4 + 1] = f2tf(v.y);
            Qs[lr*68 + ld + u*4 + 2] = f2tf(v.z); Qs[lr*68 + ld + u*4 + 3] = f2tf(v.w);
        }
    }

    float cacc[4][4];
    #pragma unroll
    for (int nt = 0; nt < 4; nt++)
      #pragma unroll
      for (int i = 0; i < 4; i++) cacc[nt][i] = 0.f;
    float rs0 = 0.f, rs1 = 0.f;

    float* wbase = w + (size_t)((b * NHEADS + h) * SEQ) * SEQ;
    const int rq0 = q0 + wm + g, rq1 = rq0 + 8;

    for (int kt = 0; kt <= qt; ++kt) {
        const int k0 = kt * 64;
        __syncthreads();
        {
            const float* ksrc = kp + (size_t)(b * SEQ + k0 + lr) * DMODEL + h * HDIM + ld;
            const float* vsrc = vp + (size_t)(b * SEQ + k0 + lr) * DMODEL + h * HDIM + ld;
            #pragma unroll
            for (int u = 0; u < 4; ++u) {
                float4 kv = *(const float4*)(ksrc + u * 4);
                Ks[lr*68 + ld + u*4 + 0] = f2tf(kv.x); Ks[lr*68 + ld + u*4 + 1] = f2tf(kv.y);
                Ks[lr*68 + ld + u*4 + 2] = f2tf(kv.z); Ks[lr*68 + ld + u*4 + 3] = f2tf(kv.w);
                float4 vv = *(const float4*)(vsrc + u * 4);
                Vt[(ld+u*4+0)*68 + lr] = f2tf(vv.x); Vt[(ld+u*4+1)*68 + lr] = f2tf(vv.y);
                Vt[(ld+u*4+2)*68 + lr] = f2tf(vv.z); Vt[(ld+u*4+3)*68 + lr] = f2tf(vv.w);
            }
        }
        __syncthreads();

        // S = Q K^T
        float s[4][4];
        #pragma unroll
        for (int nt = 0; nt < 4; nt++)
          #pragma unroll
          for (int i = 0; i < 4; i++) s[nt][i] = 0.f;
        #pragma unroll
        for (int kk = 0; kk < 64; kk += 8) {
            unsigned a[4];
            a[0] = Qs[(wm + g    ) * 68 + kk + t];
            a[1] = Qs[(wm + g + 8) * 68 + kk + t];
            a[2] = Qs[(wm + g    ) * 68 + kk + t + 4];
            a[3] = Qs[(wm + g + 8) * 68 + kk + t + 4];
            #pragma unroll
            for (int nt = 0; nt < 4; nt++) {
                unsigned bb[2];
                bb[0] = Ks[(wn + nt*8 + g) * 68 + kk + t];
                bb[1] = Ks[(wn + nt*8 + g) * 68 + kk + t + 4];
                mma8(s[nt], a, bb);
            }
        }

        // exp, mask, write w (unnormalized), accumulate rowsums, stage P
        #pragma unroll
        for (int nt = 0; nt < 4; nt++) {
            int ck = k0 + wn + nt * 8 + 2 * t;
            float e00 = __expf(s[nt][0] * 0.125f); if (ck     > rq0) e00 = 0.f;
            float e01 = __expf(s[nt][1] * 0.125f); if (ck + 1 > rq0) e01 = 0.f;
            float e10 = __expf(s[nt][2] * 0.125f); if (ck     > rq1) e10 = 0.f;
            float e11 = __expf(s[nt][3] * 0.125f); if (ck + 1 > rq1) e11 = 0.f;
            rs0 += e00 + e01;
            rs1 += e10 + e11;
            *(float2*)(wbase + (size_t)rq0 * SEQ + ck) = make_float2(e00, e01);
            *(float2*)(wbase + (size_t)rq1 * SEQ + ck) = make_float2(e10, e11);
            int pc = wn + nt * 8 + 2 * t;
            Ps[(wm + g    ) * 68 + pc    ] = f2tf(e00);
            Ps[(wm + g    ) * 68 + pc + 1] = f2tf(e01);
            Ps[(wm + g + 8) * 68 + pc    ] = f2tf(e10);
            Ps[(wm + g + 8) * 68 + pc + 1] = f2tf(e11);
        }
        __syncthreads();

        // ctx += P V
        #pragma unroll
        for (int kk = 0; kk < 64; kk += 8) {
            unsigned a[4];
            a[0] = Ps[(wm + g    ) * 68 + kk + t];
            a[1] = Ps[(wm + g + 8) * 68 + kk + t];
            a[2] = Ps[(wm + g    ) * 68 + kk + t + 4];
            a[3] = Ps[(wm + g + 8) * 68 + kk + t + 4];
            #pragma unroll
            for (int nt = 0; nt < 4; nt++) {
                unsigned bb[2];
                bb[0] = Vt[(wn + nt*8 + g) * 68 + kk + t];
                bb[1] = Vt[(wn + nt*8 + g) * 68 + kk + t + 4];
                mma8(cacc[nt], a, bb);
            }
        }
    }

    // zero-fill masked tiles of w
    {
        const int tcol = tid & 15, trow = tid >> 4;
        for (int kt = qt + 1; kt < NQT; ++kt) {
            int k0 = kt * 64;
            #pragma unroll
            for (int i = 0; i < 4; ++i) {
                int rq = q0 + trow * 4 + i;
                *(float4*)(wbase + (size_t)rq * SEQ + k0 + tcol * 4) =
                    make_float4(0.f, 0.f, 0.f, 0.f);
            }
        }
    }

    // reduce rowsums
    rs0 += __shfl_xor_sync(0xffffffffu, rs0, 1);
    rs0 += __shfl_xor_sync(0xffffffffu, rs0, 2);
    rs1 += __shfl_xor_sync(0xffffffffu, rs1, 1);
    rs1 += __shfl_xor_sync(0xffffffffu, rs1, 2);
    if (t == 0) {
        atomicAdd(&rsum_sm[wm + g], rs0);
        atomicAdd(&rsum_sm[wm + 8 + g], rs1);
    }
    __syncthreads();
    if (tid < 64) {
        float iv = 1.0f / rsum_sm[tid];
        invsm[tid] = iv;
        rowinv[(size_t)(b * NHEADS + h) * SEQ + q0 + tid] = iv;
    }
    __syncthreads();

    // store normalized ctx in concat layout
    {
        float iv0 = invsm[wm + g], iv1 = invsm[wm + g + 8];
        #pragma unroll
        for (int nt = 0; nt < 4; nt++) {
            int c = wn + nt * 8 + 2 * t;
            float* dst0 = ctx + (size_t)(b * SEQ + q0 + wm + g) * DMODEL + h * HDIM + c;
            *(float2*)dst0 = make_float2(cacc[nt][0] * iv0, cacc[nt][1] * iv0);
            float* dst1 = ctx + (size_t)(b * SEQ + q0 + wm + g + 8) * DMODEL + h * HDIM + c;
            *(float2*)dst1 = make_float2(cacc[nt][2] * iv1, cacc[nt][3] * iv1);
        }
    }
}

// ================================================================
// Normalize w rows (lower triangle only; upper already zero)
// ================================================================
__global__ __launch_bounds__(256)
void norm_w_kernel(float* __restrict__ w, const float* __restrict__ rowinv)
{
    const int r = blockIdx.x;
    const int bh = blockIdx.y;
    const float iv = rowinv[(size_t)bh * SEQ + r];
    float* row = w + ((size_t)bh * SEQ + r) * SEQ;
    const int nvec = ((r / 64 + 1) * 64) >> 2;
    for (int i = threadIdx.x; i < nvec; i += blockDim.x) {
        float4 v = *(float4*)(row + i * 4);
        v.x *= iv; v.y *= iv; v.z *= iv; v.w *= iv;
        *(float4*)(row + i * 4) = v;
    }
}

// ================================================================
// launch
// ================================================================
extern "C" void kernel_launch(void* const* d_in, const int* in_sizes, int n_in,
                              void* d_out, int out_size)
{
    const float* query = (const float*)d_in[0];
    const float* key   = (const float*)d_in[1];
    const float* value = (const float*)d_in[2];
    const float* Wk = (const float*)d_in[4];
    const float* bk = (const float*)d_in[5];
    const float* Wv = (const float*)d_in[6];
    const float* bv = (const float*)d_in[7];
    const float* Wo = (const float*)d_in[8];
    const float* bo = (const float*)d_in[9];

    float* out = (float*)d_out;
    float* w   = out + (size_t)BATCH * SEQ * DMODEL;

    float* qp  = nullptr; cudaGetSymbolAddress((void**)&qp,  g_qp);
    float* kp  = nullptr; cudaGetSymbolAddress((void**)&kp,  g_kp);
    float* vp  = nullptr; cudaGetSymbolAddress((void**)&vp,  g_vp);
    float* ctx = nullptr; cudaGetSymbolAddress((void**)&ctx, g_ctx);
    float* riv = nullptr; cudaGetSymbolAddress((void**)&riv, g_rowinv);

    cudaFuncSetAttribute(attn_tf32,
                         cudaFuncAttributeMaxDynamicSharedMemorySize,
                         ATTN_SMEM_BYTES);

    dim3 ggrid(DMODEL / 128, (BATCH * SEQ) / 128);   // (8, 32)
    gemm_tf32<<<ggrid, 256>>>(query, Wk, bk, qp);    // reference bug: q uses Wk
    gemm_tf32<<<ggrid, 256>>>(key,   Wk, bk, kp);
    gemm_tf32<<<ggrid, 256>>>(value, Wv, bv, vp);

    attn_tf32<<<dim3(NQT, NHEADS, BATCH), 256, ATTN_SMEM_BYTES>>>(
        qp, kp, vp, w, ctx, riv);

    norm_w_kernel<<<dim3(SEQ, BATCH * NHEADS), 256>>>(w, riv);

    gemm_tf32<<<ggrid, 256>>>(ctx, Wo, bo, out);
}

// round 8
// speedup vs baseline: 2.8277x; 1.4204x over previous
#include <cuda_runtime.h>
#include <cuda_fp16.h>
#include <math.h>
#include <stdint.h>

#define DMODEL 1024
#define NHEADS 16
#define HDIM   64
#define BATCH  2
#define SEQ    2048
#define NQT    (SEQ / 64)

// ---------------- scratch (no allocations allowed) ----------------
__device__ float g_qp[BATCH * SEQ * DMODEL];
__device__ float g_kp[BATCH * SEQ * DMODEL];
__device__ float g_vp[BATCH * SEQ * DMODEL];
__device__ float g_ctx[BATCH * SEQ * DMODEL];
__device__ float g_rowinv[BATCH * NHEADS * SEQ];

__device__ __forceinline__ uint32_t smem_u32(const void* p) {
    uint32_t a;
    asm("{ .reg .u64 t; cvta.to.shared.u64 t, %1; cvt.u32.u64 %0, t; }"
        : "=r"(a) : "l"(p));
    return a;
}

__device__ __forceinline__ uint32_t pack2(float a, float b) {
    __half2 h = __floats2half2_rn(a, b);
    return *(uint32_t*)&h;
}

__device__ __forceinline__ uint4 ldsm4(uint32_t addr) {
    uint4 r;
    asm volatile("ldmatrix.sync.aligned.m8n8.x4.shared.b16 {%0,%1,%2,%3}, [%4];"
                 : "=r"(r.x), "=r"(r.y), "=r"(r.z), "=r"(r.w) : "r"(addr));
    return r;
}
__device__ __forceinline__ uint4 ldsm4t(uint32_t addr) {
    uint4 r;
    asm volatile("ldmatrix.sync.aligned.m8n8.x4.trans.shared.b16 {%0,%1,%2,%3}, [%4];"
                 : "=r"(r.x), "=r"(r.y), "=r"(r.z), "=r"(r.w) : "r"(addr));
    return r;
}

// D += A(16x16) * B(16x8), fp16 in, fp32 accum
__device__ __forceinline__ void mma16(float* d, const uint4& a, uint32_t b0, uint32_t b1) {
    asm volatile(
        "mma.sync.aligned.m16n8k16.row.col.f32.f16.f16.f32 "
        "{%0,%1,%2,%3},{%4,%5,%6,%7},{%8,%9},{%0,%1,%2,%3};"
        : "+f"(d[0]), "+f"(d[1]), "+f"(d[2]), "+f"(d[3])
        : "r"(a.x), "r"(a.y), "r"(a.z), "r"(a.w), "r"(b0), "r"(b1));
}

// ================================================================
// fp16 GEMM: C[M,1024] = X[M,1024] @ W[1024,1024]^T + bias
// 128x128 tile, BK=16, 256 threads = 8 warps (2m x 4n), warp 64x32
// smem pitch 24 halves (48B): conflict-free ldmatrix
// ================================================================
__global__ __launch_bounds__(256, 2)
void gemm_h(const float* __restrict__ X, const float* __restrict__ W,
            const float* __restrict__ bias, float* __restrict__ C)
{
    __shared__ __half Xs[128 * 24];
    __shared__ __half Ws[128 * 24];

    const int tid = threadIdx.x, lane = tid & 31, wid = tid >> 5;
    const int bm = blockIdx.y * 128, bn = blockIdx.x * 128;
    const int wm = (wid & 1) * 64, wn = (wid >> 1) * 32;
    const int g = lane >> 2, t = lane & 3;

    float acc[4][4][4];
    #pragma unroll
    for (int mt = 0; mt < 4; mt++)
      #pragma unroll
      for (int nt = 0; nt < 4; nt++)
        #pragma unroll
        for (int i = 0; i < 4; i++) acc[mt][nt][i] = 0.f;

    const int lr = tid >> 1, lk8 = (tid & 1) * 8;
    const float* xp = X + (size_t)(bm + lr) * DMODEL + lk8;
    const float* wp = W + (size_t)(bn + lr) * DMODEL + lk8;

    const uint32_t xb = smem_u32(Xs), wb = smem_u32(Ws);
    const uint32_t xfr = xb + (((wm + (lane & 15)) * 24 + (lane >> 4) * 8) << 1);
    const uint32_t wfr = wb + (((wn + (lane & 15)) * 24 + (lane >> 4) * 8) << 1);
    __half* sx = Xs + lr * 24 + lk8;
    __half* sw = Ws + lr * 24 + lk8;

    float4 px0 = *(const float4*)(xp), px1 = *(const float4*)(xp + 4);
    float4 pw0 = *(const float4*)(wp), pw1 = *(const float4*)(wp + 4);

    for (int kt = 0; kt < DMODEL / 16; ++kt) {
        *(uint4*)sx = make_uint4(pack2(px0.x, px0.y), pack2(px0.z, px0.w),
                                 pack2(px1.x, px1.y), pack2(px1.z, px1.w));
        *(uint4*)sw = make_uint4(pack2(pw0.x, pw0.y), pack2(pw0.z, pw0.w),
                                 pack2(pw1.x, pw1.y), pack2(pw1.z, pw1.w));
        __syncthreads();

        if (kt + 1 < DMODEL / 16) {
            const float* xn = xp + (kt + 1) * 16;
            const float* wn_ = wp + (kt + 1) * 16;
            px0 = *(const float4*)(xn);     px1 = *(const float4*)(xn + 4);
            pw0 = *(const float4*)(wn_);    pw1 = *(const float4*)(wn_ + 4);
        }

        #pragma unroll
        for (int nh = 0; nh < 2; ++nh) {
            uint4 bfr = ldsm4(wfr + nh * (16 * 24 * 2));
            #pragma unroll
            for (int mt = 0; mt < 4; ++mt) {
                uint4 afr = ldsm4(xfr + mt * (16 * 24 * 2));
                mma16(acc[mt][nh * 2],     afr, bfr.x, bfr.z);
                mma16(acc[mt][nh * 2 + 1], afr, bfr.y, bfr.w);
            }
        }
        __syncthreads();
    }

    #pragma unroll
    for (int mt = 0; mt < 4; mt++) {
        int r0 = bm + wm + mt * 16 + g;
        #pragma unroll
        for (int nt = 0; nt < 4; nt++) {
            int c = bn + wn + nt * 8 + 2 * t;
            float2 bb = *(const float2*)(bias + c);
            *(float2*)(C + (size_t)r0 * DMODEL + c) =
                make_float2(acc[mt][nt][0] + bb.x, acc[mt][nt][1] + bb.y);
            *(float2*)(C + (size_t)(r0 + 8) * DMODEL + c) =
                make_float2(acc[mt][nt][2] + bb.x, acc[mt][nt][3] + bb.y);
        }
    }
}

// ================================================================
// Fused causal attention, fp16 mma + ldmatrix.
// Block = (b,h,64-row q-tile), 256 thr = 8 warps (4 row x 2 col).
// smem pitch 72 halves (144B): conflict-free for ldsm and ldsm.trans
// ================================================================
__global__ __launch_bounds__(256, 2)
void attn_h(const float* __restrict__ qp, const float* __restrict__ kp,
            const float* __restrict__ vp, float* __restrict__ w,
            float* __restrict__ ctx, float* __restrict__ rowinv)
{
    __shared__ __half Qs[64 * 72];
    __shared__ __half Ks[64 * 72];
    __shared__ __half Vs[64 * 72];   // natural [key][d]
    __shared__ __half Ps[64 * 72];
    __shared__ float rsum_sm[64];
    __shared__ float invsm[64];

    const int qt = (int)gridDim.x - 1 - (int)blockIdx.x;
    const int h = blockIdx.y, b = blockIdx.z;
    const int q0 = qt * 64;
    const int tid = threadIdx.x, lane = tid & 31, wid = tid >> 5;
    const int wm = (wid & 3) * 16, wn = (wid >> 2) * 32;
    const int g = lane >> 2, t = lane & 3;

    if (tid < 64) rsum_sm[tid] = 0.f;

    const uint32_t qb = smem_u32(Qs), kb = smem_u32(Ks);
    const uint32_t vb = smem_u32(Vs), pb = smem_u32(Ps);
    const uint32_t qfr = qb + (((wm + (lane & 15)) * 72 + (lane >> 4) * 8) << 1);
    const uint32_t pfr = pb + (((wm + (lane & 15)) * 72 + (lane >> 4) * 8) << 1);
    const uint32_t kfr = kb + (((wn + (lane & 15)) * 72 + (lane >> 4) * 8) << 1);
    const uint32_t vfr = vb + (((lane & 15) * 72 + wn + (lane >> 4) * 8) << 1);

    const int lr = tid >> 2, ldc = (tid & 3) * 16;

    // load Q tile [row][d]
    {
        const float* src = qp + (size_t)(b * SEQ + q0 + lr) * DMODEL + h * HDIM + ldc;
        #pragma unroll
        for (int u = 0; u < 4; ++u) {
            float4 v = *(const float4*)(src + u * 4);
            *(uint2*)(Qs + lr * 72 + ldc + u * 4) =
                make_uint2(pack2(v.x, v.y), pack2(v.z, v.w));
        }
    }

    float cacc[4][4];
    #pragma unroll
    for (int nt = 0; nt < 4; nt++)
      #pragma unroll
      for (int i = 0; i < 4; i++) cacc[nt][i] = 0.f;
    float rs0 = 0.f, rs1 = 0.f;

    float* wbase = w + (size_t)((b * NHEADS + h) * SEQ) * SEQ;
    const int rq0 = q0 + wm + g, rq1 = rq0 + 8;

    // prefetch K/V tile 0
    const float* kp0 = kp + (size_t)(b * SEQ + lr) * DMODEL + h * HDIM + ldc;
    const float* vp0 = vp + (size_t)(b * SEQ + lr) * DMODEL + h * HDIM + ldc;
    float4 rk[4], rv[4];
    #pragma unroll
    for (int u = 0; u < 4; ++u) {
        rk[u] = *(const float4*)(kp0 + u * 4);
        rv[u] = *(const float4*)(vp0 + u * 4);
    }

    for (int kt = 0; kt <= qt; ++kt) {
        __syncthreads();   // prior readers of Ks/Vs/Ps done
        #pragma unroll
        for (int u = 0; u < 4; ++u) {
            *(uint2*)(Ks + lr * 72 + ldc + u * 4) =
                make_uint2(pack2(rk[u].x, rk[u].y), pack2(rk[u].z, rk[u].w));
            *(uint2*)(Vs + lr * 72 + ldc + u * 4) =
                make_uint2(pack2(rv[u].x, rv[u].y), pack2(rv[u].z, rv[u].w));
        }
        if (kt < qt) {
            const float* kn = kp0 + (size_t)(kt + 1) * 64 * DMODEL;
            const float* vn = vp0 + (size_t)(kt + 1) * 64 * DMODEL;
            #pragma unroll
            for (int u = 0; u < 4; ++u) {
                rk[u] = *(const float4*)(kn + u * 4);
                rv[u] = *(const float4*)(vn + u * 4);
            }
        }
        __syncthreads();

        // GEMM1: S = Q K^T
        float s[4][4];
        #pragma unroll
        for (int nt = 0; nt < 4; nt++)
          #pragma unroll
          for (int i = 0; i < 4; i++) s[nt][i] = 0.f;
        #pragma unroll
        for (int kc = 0; kc < 64; kc += 16) {
            uint4 afr = ldsm4(qfr + (kc << 1));
            #pragma unroll
            for (int nh = 0; nh < 2; ++nh) {
                uint4 bfr = ldsm4(kfr + nh * (16 * 72 * 2) + (kc << 1));
                mma16(s[nh * 2],     afr, bfr.x, bfr.z);
                mma16(s[nh * 2 + 1], afr, bfr.y, bfr.w);
            }
        }

        // exp, mask, write w (unnormalized), rowsums, stage P (fp16)
        const int k0 = kt * 64;
        #pragma unroll
        for (int nt = 0; nt < 4; nt++) {
            int ck = k0 + wn + nt * 8 + 2 * t;
            float e00 = __expf(s[nt][0] * 0.125f); if (ck     > rq0) e00 = 0.f;
            float e01 = __expf(s[nt][1] * 0.125f); if (ck + 1 > rq0) e01 = 0.f;
            float e10 = __expf(s[nt][2] * 0.125f); if (ck     > rq1) e10 = 0.f;
            float e11 = __expf(s[nt][3] * 0.125f); if (ck + 1 > rq1) e11 = 0.f;
            rs0 += e00 + e01;
            rs1 += e10 + e11;
            *(float2*)(wbase + (size_t)rq0 * SEQ + ck) = make_float2(e00, e01);
            *(float2*)(wbase + (size_t)rq1 * SEQ + ck) = make_float2(e10, e11);
            int pc = wn + nt * 8 + 2 * t;
            *(uint32_t*)(Ps + (wm + g) * 72 + pc)     = pack2(e00, e01);
            *(uint32_t*)(Ps + (wm + g + 8) * 72 + pc) = pack2(e10, e11);
        }
        __syncthreads();   // Ps visible to all warps

        // GEMM2: ctx += P V  (B fragments via trans ldmatrix on natural V)
        #pragma unroll
        for (int kc = 0; kc < 64; kc += 16) {
            uint4 afr = ldsm4(pfr + (kc << 1));
            #pragma unroll
            for (int nh = 0; nh < 2; ++nh) {
                uint4 bfr = ldsm4t(vfr + ((kc * 72 + nh * 16) << 1));
                mma16(cacc[nh * 2],     afr, bfr.x, bfr.y);
                mma16(cacc[nh * 2 + 1], afr, bfr.z, bfr.w);
            }
        }
    }

    // zero-fill masked tiles of w (d_out is poisoned)
    {
        const int tcol = tid & 15, trow = tid >> 4;
        for (int kt = qt + 1; kt < NQT; ++kt) {
            int k0 = kt * 64;
            #pragma unroll
            for (int i = 0; i < 4; ++i) {
                int rq = q0 + trow * 4 + i;
                *(float4*)(wbase + (size_t)rq * SEQ + k0 + tcol * 4) =
                    make_float4(0.f, 0.f, 0.f, 0.f);
            }
        }
    }

    // reduce rowsums: lanes t=0..3 of each row-group hold partials
    rs0 += __shfl_xor_sync(0xffffffffu, rs0, 1);
    rs0 += __shfl_xor_sync(0xffffffffu, rs0, 2);
    rs1 += __shfl_xor_sync(0xffffffffu, rs1, 1);
    rs1 += __shfl_xor_sync(0xffffffffu, rs1, 2);
    if (t == 0) {
        atomicAdd(&rsum_sm[wm + g], rs0);
        atomicAdd(&rsum_sm[wm + 8 + g], rs1);
    }
    __syncthreads();
    if (tid < 64) {
        float iv = 1.0f / rsum_sm[tid];
        invsm[tid] = iv;
        rowinv[(size_t)(b * NHEADS + h) * SEQ + q0 + tid] = iv;
    }
    __syncthreads();

    // store normalized ctx in concat layout [b, s, h*64+d]
    {
        float iv0 = invsm[wm + g], iv1 = invsm[wm + g + 8];
        #pragma unroll
        for (int nt = 0; nt < 4; nt++) {
            int c = wn + nt * 8 + 2 * t;
            float* dst0 = ctx + (size_t)(b * SEQ + q0 + wm + g) * DMODEL + h * HDIM + c;
            *(float2*)dst0 = make_float2(cacc[nt][0] * iv0, cacc[nt][1] * iv0);
            float* dst1 = ctx + (size_t)(b * SEQ + q0 + wm + g + 8) * DMODEL + h * HDIM + c;
            *(float2*)dst1 = make_float2(cacc[nt][2] * iv1, cacc[nt][3] * iv1);
        }
    }
}

// ================================================================
// Normalize w rows (lower triangle only; upper already zero)
// ================================================================
__global__ __launch_bounds__(256)
void norm_w_kernel(float* __restrict__ w, const float* __restrict__ rowinv)
{
    const int r = blockIdx.x;
    const int bh = blockIdx.y;
    const float iv = rowinv[(size_t)bh * SEQ + r];
    float* row = w + ((size_t)bh * SEQ + r) * SEQ;
    const int nvec = ((r / 64 + 1) * 64) >> 2;
    for (int i = threadIdx.x; i < nvec; i += blockDim.x) {
        float4 v = *(float4*)(row + i * 4);
        v.x *= iv; v.y *= iv; v.z *= iv; v.w *= iv;
        *(float4*)(row + i * 4) = v;
    }
}

// ================================================================
// launch
// ================================================================
extern "C" void kernel_launch(void* const* d_in, const int* in_sizes, int n_in,
                              void* d_out, int out_size)
{
    const float* query = (const float*)d_in[0];
    const float* key   = (const float*)d_in[1];
    const float* value = (const float*)d_in[2];
    const float* Wk = (const float*)d_in[4];
    const float* bk = (const float*)d_in[5];
    const float* Wv = (const float*)d_in[6];
    const float* bv = (const float*)d_in[7];
    const float* Wo = (const float*)d_in[8];
    const float* bo = (const float*)d_in[9];

    float* out = (float*)d_out;
    float* w   = out + (size_t)BATCH * SEQ * DMODEL;

    float* qp  = nullptr; cudaGetSymbolAddress((void**)&qp,  g_qp);
    float* kp  = nullptr; cudaGetSymbolAddress((void**)&kp,  g_kp);
    float* vp  = nullptr; cudaGetSymbolAddress((void**)&vp,  g_vp);
    float* ctx = nullptr; cudaGetSymbolAddress((void**)&ctx, g_ctx);
    float* riv = nullptr; cudaGetSymbolAddress((void**)&riv, g_rowinv);

    dim3 ggrid(DMODEL / 128, (BATCH * SEQ) / 128);   // (8, 32)
    gemm_h<<<ggrid, 256>>>(query, Wk, bk, qp);       // ref bug: q uses Wk
    gemm_h<<<ggrid, 256>>>(key,   Wk, bk, kp);
    gemm_h<<<ggrid, 256>>>(value, Wv, bv, vp);

    attn_h<<<dim3(NQT, NHEADS, BATCH), 256>>>(qp, kp, vp, w, ctx, riv);

    norm_w_kernel<<<dim3(SEQ, BATCH * NHEADS), 256>>>(w, riv);

    gemm_h<<<ggrid, 256>>>(ctx, Wo, bo, out);
}

// round 9
// speedup vs baseline: 3.2900x; 1.1635x over previous
#include <cuda_runtime.h>
#include <cuda_fp16.h>
#include <math.h>
#include <stdint.h>

#define DMODEL 1024
#define NHEADS 16
#define HDIM   64
#define BATCH  2
#define SEQ    2048
#define NQT    (SEQ / 64)

// ---------------- scratch (no allocations allowed) ----------------
__device__ __half g_qp[BATCH * SEQ * DMODEL];
__device__ __half g_kp[BATCH * SEQ * DMODEL];
__device__ __half g_vp[BATCH * SEQ * DMODEL];
__device__ float  g_ctx[BATCH * SEQ * DMODEL];
__device__ float  g_rowinv[BATCH * NHEADS * SEQ];

__device__ __forceinline__ uint32_t smem_u32(const void* p) {
    uint32_t a;
    asm("{ .reg .u64 t; cvta.to.shared.u64 t, %1; cvt.u32.u64 %0, t; }"
        : "=r"(a) : "l"(p));
    return a;
}
__device__ __forceinline__ uint32_t pack2(float a, float b) {
    __half2 h = __floats2half2_rn(a, b);
    return *(uint32_t*)&h;
}
__device__ __forceinline__ uint4 ldsm4(uint32_t addr) {
    uint4 r;
    asm volatile("ldmatrix.sync.aligned.m8n8.x4.shared.b16 {%0,%1,%2,%3}, [%4];"
                 : "=r"(r.x), "=r"(r.y), "=r"(r.z), "=r"(r.w) : "r"(addr));
    return r;
}
__device__ __forceinline__ uint4 ldsm4t(uint32_t addr) {
    uint4 r;
    asm volatile("ldmatrix.sync.aligned.m8n8.x4.trans.shared.b16 {%0,%1,%2,%3}, [%4];"
                 : "=r"(r.x), "=r"(r.y), "=r"(r.z), "=r"(r.w) : "r"(addr));
    return r;
}
__device__ __forceinline__ void mma16(float* d, const uint4& a, uint32_t b0, uint32_t b1) {
    asm volatile(
        "mma.sync.aligned.m16n8k16.row.col.f32.f16.f16.f32 "
        "{%0,%1,%2,%3},{%4,%5,%6,%7},{%8,%9},{%0,%1,%2,%3};"
        : "+f"(d[0]), "+f"(d[1]), "+f"(d[2]), "+f"(d[3])
        : "r"(a.x), "r"(a.y), "r"(a.z), "r"(a.w), "r"(b0), "r"(b1));
}
#define CP16(dst, src) \
    asm volatile("cp.async.cg.shared.global [%0], [%1], 16;" :: "r"(dst), "l"(src))
#define CP_COMMIT() asm volatile("cp.async.commit_group;" ::: "memory")
#define CP_WAIT0()  asm volatile("cp.async.wait_group 0;" ::: "memory")

// ================================================================
// fp16 GEMM: C[M,1024] = X[M,1024] @ W[1024,1024]^T + bias
// (proven R8 structure; templated epilogue: fp32 or fp16 output)
// ================================================================
template <bool HOUT>
__global__ __launch_bounds__(256, 2)
void gemm_h(const float* __restrict__ X, const float* __restrict__ W,
            const float* __restrict__ bias, void* __restrict__ Cv)
{
    __shared__ __half Xs[128 * 24];
    __shared__ __half Ws[128 * 24];

    const int tid = threadIdx.x, lane = tid & 31, wid = tid >> 5;
    const int bm = blockIdx.y * 128, bn = blockIdx.x * 128;
    const int wm = (wid & 1) * 64, wn = (wid >> 1) * 32;
    const int g = lane >> 2, t = lane & 3;

    float acc[4][4][4];
    #pragma unroll
    for (int mt = 0; mt < 4; mt++)
      #pragma unroll
      for (int nt = 0; nt < 4; nt++)
        #pragma unroll
        for (int i = 0; i < 4; i++) acc[mt][nt][i] = 0.f;

    const int lr = tid >> 1, lk8 = (tid & 1) * 8;
    const float* xp = X + (size_t)(bm + lr) * DMODEL + lk8;
    const float* wp = W + (size_t)(bn + lr) * DMODEL + lk8;

    const uint32_t xb = smem_u32(Xs), wb = smem_u32(Ws);
    const uint32_t xfr = xb + (((wm + (lane & 15)) * 24 + (lane >> 4) * 8) << 1);
    const uint32_t wfr = wb + (((wn + (lane & 15)) * 24 + (lane >> 4) * 8) << 1);
    __half* sx = Xs + lr * 24 + lk8;
    __half* sw = Ws + lr * 24 + lk8;

    float4 px0 = *(const float4*)(xp), px1 = *(const float4*)(xp + 4);
    float4 pw0 = *(const float4*)(wp), pw1 = *(const float4*)(wp + 4);

    for (int kt = 0; kt < DMODEL / 16; ++kt) {
        *(uint4*)sx = make_uint4(pack2(px0.x, px0.y), pack2(px0.z, px0.w),
                                 pack2(px1.x, px1.y), pack2(px1.z, px1.w));
        *(uint4*)sw = make_uint4(pack2(pw0.x, pw0.y), pack2(pw0.z, pw0.w),
                                 pack2(pw1.x, pw1.y), pack2(pw1.z, pw1.w));
        __syncthreads();

        if (kt + 1 < DMODEL / 16) {
            const float* xn = xp + (kt + 1) * 16;
            const float* wn_ = wp + (kt + 1) * 16;
            px0 = *(const float4*)(xn);     px1 = *(const float4*)(xn + 4);
            pw0 = *(const float4*)(wn_);    pw1 = *(const float4*)(wn_ + 4);
        }

        #pragma unroll
        for (int nh = 0; nh < 2; ++nh) {
            uint4 bfr = ldsm4(wfr + nh * (16 * 24 * 2));
            #pragma unroll
            for (int mt = 0; mt < 4; ++mt) {
                uint4 afr = ldsm4(xfr + mt * (16 * 24 * 2));
                mma16(acc[mt][nh * 2],     afr, bfr.x, bfr.z);
                mma16(acc[mt][nh * 2 + 1], afr, bfr.y, bfr.w);
            }
        }
        __syncthreads();
    }

    #pragma unroll
    for (int mt = 0; mt < 4; mt++) {
        int r0 = bm + wm + mt * 16 + g;
        #pragma unroll
        for (int nt = 0; nt < 4; nt++) {
            int c = bn + wn + nt * 8 + 2 * t;
            float2 bb = *(const float2*)(bias + c);
            float o00 = acc[mt][nt][0] + bb.x, o01 = acc[mt][nt][1] + bb.y;
            float o10 = acc[mt][nt][2] + bb.x, o11 = acc[mt][nt][3] + bb.y;
            if (HOUT) {
                __half* C = (__half*)Cv;
                *(uint32_t*)(C + (size_t)r0 * DMODEL + c)       = pack2(o00, o01);
                *(uint32_t*)(C + (size_t)(r0 + 8) * DMODEL + c) = pack2(o10, o11);
            } else {
                float* C = (float*)Cv;
                *(float2*)(C + (size_t)r0 * DMODEL + c)       = make_float2(o00, o01);
                *(float2*)(C + (size_t)(r0 + 8) * DMODEL + c) = make_float2(o10, o11);
            }
        }
    }
}

// ================================================================
// Fused causal attention: block = 128 q-rows x 64-key tiles.
// 8 warps (4m x 2n), warp tile 32x32. fp16 in smem, cp.async staging,
// double-buffered K/V. Pitch 72 halves: conflict-free ldsm/ldsm.trans.
// smem (halves): Q[128*72]@0  K0@9216 K1@13824  V0@18432 V1@23040
//                P[128*72]@27648 ; floats rsum[128] inv[128] @byte 73728
// ================================================================
#define SK0 9216
#define SK1 13824
#define SV0 18432
#define SV1 23040
#define SP  27648
#define ATTN_SMEM (73728 + 256 * 4)

__global__ __launch_bounds__(256, 2)
void attn_h(const __half* __restrict__ qp, const __half* __restrict__ kp,
            const __half* __restrict__ vp, float* __restrict__ w,
            float* __restrict__ ctx, float* __restrict__ rowinv)
{
    extern __shared__ __half hs[];
    float* rsum_sm = (float*)(hs + 36864);
    float* invsm   = rsum_sm + 128;

    const int qt = 15 - (int)blockIdx.x;      // big tiles first
    const int h = blockIdx.y, b = blockIdx.z;
    const int q0 = qt * 128;
    const int nkt = 2 * qt + 2;               // 64-key tiles this block touches
    const int tid = threadIdx.x, lane = tid & 31, wid = tid >> 5;
    const int wm = (wid & 3) * 32, wn = (wid >> 2) * 32;
    const int g = lane >> 2, t = lane & 3;
    const uint32_t sb = smem_u32(hs);

    if (tid < 128) rsum_sm[tid] = 0.f;

    // fragment base addresses
    const uint32_t qfr = sb + (((wm + (lane & 15)) * 72 + (lane >> 4) * 8) << 1);
    const uint32_t pfr = sb + ((SP + (wm + (lane & 15)) * 72 + (lane >> 4) * 8) << 1);
    const uint32_t kfroff = (((wn + (lane & 15)) * 72 + (lane >> 4) * 8) << 1);
    const uint32_t vfroff = (((lane & 15) * 72 + wn + (lane >> 4) * 8) << 1);

    // staging maps
    const int qr = tid >> 1, qc = (tid & 1) * 32;          // Q: 128 rows x 64
    const int kr = tid >> 2, kc = (tid & 3) * 16;          // K/V: 64 rows x 64
    const __half* ksrc0 = kp + (size_t)(b * SEQ + kr) * DMODEL + h * HDIM + kc;
    const __half* vsrc0 = vp + (size_t)(b * SEQ + kr) * DMODEL + h * HDIM + kc;

    // prologue: Q + K/V tile 0
    {
        uint32_t qd = sb + ((qr * 72 + qc) << 1);
        const __half* qs = qp + (size_t)(b * SEQ + q0 + qr) * DMODEL + h * HDIM + qc;
        CP16(qd, qs); CP16(qd + 16, qs + 8); CP16(qd + 32, qs + 16); CP16(qd + 48, qs + 24);
        uint32_t kd = sb + ((SK0 + kr * 72 + kc) << 1);
        uint32_t vd = sb + ((SV0 + kr * 72 + kc) << 1);
        CP16(kd, ksrc0); CP16(kd + 16, ksrc0 + 8);
        CP16(vd, vsrc0); CP16(vd + 16, vsrc0 + 8);
        CP_COMMIT();
    }

    float cacc[2][4][4];
    #pragma unroll
    for (int m = 0; m < 2; m++)
      #pragma unroll
      for (int nt = 0; nt < 4; nt++)
        #pragma unroll
        for (int i = 0; i < 4; i++) cacc[m][nt][i] = 0.f;
    float rs[2][2] = {{0.f, 0.f}, {0.f, 0.f}};

    float* wbase = w + (size_t)((b * NHEADS + h) * SEQ) * SEQ;

    for (int kt = 0; kt < nkt; ++kt) {
        CP_WAIT0();
        __syncthreads();          // tile kt resident; all reads of other buf done
        const int buf = kt & 1;

        if (kt + 1 < nkt) {       // prefetch tile kt+1 into other buffer
            const int nb = buf ^ 1;
            uint32_t kd = sb + (((nb ? SK1 : SK0) + kr * 72 + kc) << 1);
            uint32_t vd = sb + (((nb ? SV1 : SV0) + kr * 72 + kc) << 1);
            const __half* ks = ksrc0 + (size_t)(kt + 1) * 64 * DMODEL;
            const __half* vs = vsrc0 + (size_t)(kt + 1) * 64 * DMODEL;
            CP16(kd, ks); CP16(kd + 16, ks + 8);
            CP16(vd, vs); CP16(vd + 16, vs + 8);
            CP_COMMIT();
        }

        const uint32_t kfr = sb + (((buf ? SK1 : SK0)) << 1) + kfroff;
        const uint32_t vfr = sb + (((buf ? SV1 : SV0)) << 1) + vfroff;

        // GEMM1: S[128x64] = Q Kt^T
        float s[2][4][4];
        #pragma unroll
        for (int m = 0; m < 2; m++)
          #pragma unroll
          for (int nt = 0; nt < 4; nt++)
            #pragma unroll
            for (int i = 0; i < 4; i++) s[m][nt][i] = 0.f;
        #pragma unroll
        for (int kd = 0; kd < 64; kd += 16) {
            uint4 a0 = ldsm4(qfr + (kd << 1));
            uint4 a1 = ldsm4(qfr + ((16 * 72 + kd) << 1));
            #pragma unroll
            for (int nb = 0; nb < 2; ++nb) {
                uint4 bf = ldsm4(kfr + ((nb * 16 * 72 + kd) << 1));
                mma16(s[0][nb * 2],     a0, bf.x, bf.z);
                mma16(s[0][nb * 2 + 1], a0, bf.y, bf.w);
                mma16(s[1][nb * 2],     a1, bf.x, bf.z);
                mma16(s[1][nb * 2 + 1], a1, bf.y, bf.w);
            }
        }

        // exp, mask, write unnormalized w, rowsums, stage P (fp16)
        const int k0 = kt * 64;
        #pragma unroll
        for (int m = 0; m < 2; m++) {
            const int r0g = q0 + wm + m * 16 + g, r1g = r0g + 8;
            #pragma unroll
            for (int nt = 0; nt < 4; nt++) {
                int ck = k0 + wn + nt * 8 + 2 * t;
                float e00 = __expf(s[m][nt][0] * 0.125f); if (ck     > r0g) e00 = 0.f;
                float e01 = __expf(s[m][nt][1] * 0.125f); if (ck + 1 > r0g) e01 = 0.f;
                float e10 = __expf(s[m][nt][2] * 0.125f); if (ck     > r1g) e10 = 0.f;
                float e11 = __expf(s[m][nt][3] * 0.125f); if (ck + 1 > r1g) e11 = 0.f;
                rs[m][0] += e00 + e01;
                rs[m][1] += e10 + e11;
                *(float2*)(wbase + (size_t)r0g * SEQ + ck) = make_float2(e00, e01);
                *(float2*)(wbase + (size_t)r1g * SEQ + ck) = make_float2(e10, e11);
                int pc = wn + nt * 8 + 2 * t;
                *(uint32_t*)(hs + SP + (wm + m * 16 + g) * 72 + pc)     = pack2(e00, e01);
                *(uint32_t*)(hs + SP + (wm + m * 16 + g + 8) * 72 + pc) = pack2(e10, e11);
            }
        }
        __syncthreads();          // P visible

        // GEMM2: ctx += P V   (V natural layout, B via ldsm.trans)
        #pragma unroll
        for (int kk = 0; kk < 64; kk += 16) {
            uint4 a0 = ldsm4(pfr + (kk << 1));
            uint4 a1 = ldsm4(pfr + ((16 * 72 + kk) << 1));
            #pragma unroll
            for (int nb = 0; nb < 2; ++nb) {
                uint4 bf = ldsm4t(vfr + ((kk * 72 + nb * 16) << 1));
                mma16(cacc[0][nb * 2],     a0, bf.x, bf.y);
                mma16(cacc[0][nb * 2 + 1], a0, bf.z, bf.w);
                mma16(cacc[1][nb * 2],     a1, bf.x, bf.y);
                mma16(cacc[1][nb * 2 + 1], a1, bf.z, bf.w);
            }
        }
    }

    // zero-fill masked tiles of w (d_out is poisoned)
    {
        const int tcol = tid & 15, trow = tid >> 4;
        for (int kt2 = nkt; kt2 < NQT; ++kt2) {
            int k0 = kt2 * 64;
            #pragma unroll
            for (int rr = 0; rr < 8; ++rr) {
                int row = q0 + trow + rr * 16;
                *(float4*)(wbase + (size_t)row * SEQ + k0 + tcol * 4) =
                    make_float4(0.f, 0.f, 0.f, 0.f);
            }
        }
    }

    // reduce rowsums across t-lanes, then across n-warp-groups via atomics
    #pragma unroll
    for (int m = 0; m < 2; m++)
      #pragma unroll
      for (int hf = 0; hf < 2; hf++) {
          rs[m][hf] += __shfl_xor_sync(0xffffffffu, rs[m][hf], 1);
          rs[m][hf] += __shfl_xor_sync(0xffffffffu, rs[m][hf], 2);
      }
    if (t == 0) {
        atomicAdd(&rsum_sm[wm + g],          rs[0][0]);
        atomicAdd(&rsum_sm[wm + g + 8],      rs[0][1]);
        atomicAdd(&rsum_sm[wm + 16 + g],     rs[1][0]);
        atomicAdd(&rsum_sm[wm + 16 + g + 8], rs[1][1]);
    }
    __syncthreads();
    if (tid < 128) {
        float iv = 1.0f / rsum_sm[tid];
        invsm[tid] = iv;
        rowinv[(size_t)(b * NHEADS + h) * SEQ + q0 + tid] = iv;
    }
    __syncthreads();

    // store normalized ctx in concat layout [b, s, h*64+d]
    #pragma unroll
    for (int m = 0; m < 2; m++) {
        float iv0 = invsm[wm + m * 16 + g], iv1 = invsm[wm + m * 16 + g + 8];
        int r0 = q0 + wm + m * 16 + g;
        #pragma unroll
        for (int nt = 0; nt < 4; nt++) {
            int c = h * HDIM + wn + nt * 8 + 2 * t;
            *(float2*)(ctx + (size_t)(b * SEQ + r0) * DMODEL + c) =
                make_float2(cacc[m][nt][0] * iv0, cacc[m][nt][1] * iv0);
            *(float2*)(ctx + (size_t)(b * SEQ + r0 + 8) * DMODEL + c) =
                make_float2(cacc[m][nt][2] * iv1, cacc[m][nt][3] * iv1);
        }
    }
}

// ================================================================
// Normalize w rows (lower triangle only), warp per row
// ================================================================
__global__ __launch_bounds__(256)
void norm_w_kernel(float* __restrict__ w, const float* __restrict__ rowinv)
{
    const int r  = blockIdx.x * 8 + (threadIdx.x >> 5);
    const int bh = blockIdx.y;
    const int lane = threadIdx.x & 31;
    const float iv = rowinv[(size_t)bh * SEQ + r];
    float4* row = (float4*)(w + ((size_t)bh * SEQ + r) * SEQ);
    const int nvec = ((r >> 6) + 1) << 4;   // (r/64+1)*64/4
    for (int i = lane; i < nvec; i += 32) {
        float4 v = row[i];
        v.x *= iv; v.y *= iv; v.z *= iv; v.w *= iv;
        row[i] = v;
    }
}

// ================================================================
// launch
// ================================================================
extern "C" void kernel_launch(void* const* d_in, const int* in_sizes, int n_in,
                              void* d_out, int out_size)
{
    const float* query = (const float*)d_in[0];
    const float* key   = (const float*)d_in[1];
    const float* value = (const float*)d_in[2];
    const float* Wk = (const float*)d_in[4];
    const float* bk = (const float*)d_in[5];
    const float* Wv = (const float*)d_in[6];
    const float* bv = (const float*)d_in[7];
    const float* Wo = (const float*)d_in[8];
    const float* bo = (const float*)d_in[9];

    float* out = (float*)d_out;
    float* w   = out + (size_t)BATCH * SEQ * DMODEL;

    __half* qp = nullptr; cudaGetSymbolAddress((void**)&qp, g_qp);
    __half* kp = nullptr; cudaGetSymbolAddress((void**)&kp, g_kp);
    __half* vp = nullptr; cudaGetSymbolAddress((void**)&vp, g_vp);
    float* ctx = nullptr; cudaGetSymbolAddress((void**)&ctx, g_ctx);
    float* riv = nullptr; cudaGetSymbolAddress((void**)&riv, g_rowinv);

    cudaFuncSetAttribute(attn_h,
                         cudaFuncAttributeMaxDynamicSharedMemorySize,
                         ATTN_SMEM);

    dim3 ggrid(DMODEL / 128, (BATCH * SEQ) / 128);   // (8, 32)
    gemm_h<true><<<ggrid, 256>>>(query, Wk, bk, qp);  // ref bug: q uses Wk
    gemm_h<true><<<ggrid, 256>>>(key,   Wk, bk, kp);
    gemm_h<true><<<ggrid, 256>>>(value, Wv, bv, vp);

    attn_h<<<dim3(SEQ / 128, NHEADS, BATCH), 256, ATTN_SMEM>>>(
        qp, kp, vp, w, ctx, riv);

    norm_w_kernel<<<dim3(SEQ / 8, BATCH * NHEADS), 256>>>(w, riv);

    gemm_h<false><<<ggrid, 256>>>(ctx, Wo, bo, out);
}

// round 10
// speedup vs baseline: 3.8291x; 1.1639x over previous
#include <cuda_runtime.h>
#include <cuda_fp16.h>
#include <math.h>
#include <stdint.h>

#define DMODEL 1024
#define NHEADS 16
#define HDIM   64
#define BATCH  2
#define SEQ    2048
#define NQT    (SEQ / 64)

// ---------------- scratch (no allocations allowed) ----------------
__device__ __half g_xq[BATCH * SEQ * DMODEL];   // fp16 inputs
__device__ __half g_xk[BATCH * SEQ * DMODEL];
__device__ __half g_xv[BATCH * SEQ * DMODEL];
__device__ __half g_whk[DMODEL * DMODEL];       // fp16 weights
__device__ __half g_whv[DMODEL * DMODEL];
__device__ __half g_who[DMODEL * DMODEL];
__device__ __half g_qp[BATCH * SEQ * DMODEL];   // projected q/k/v
__device__ __half g_kp[BATCH * SEQ * DMODEL];
__device__ __half g_vp[BATCH * SEQ * DMODEL];
__device__ __half g_ctx[BATCH * SEQ * DMODEL];  // attention context (fp16)

__device__ __forceinline__ uint32_t smem_u32(const void* p) {
    uint32_t a;
    asm("{ .reg .u64 t; cvta.to.shared.u64 t, %1; cvt.u32.u64 %0, t; }"
        : "=r"(a) : "l"(p));
    return a;
}
__device__ __forceinline__ uint32_t pack2(float a, float b) {
    __half2 h = __floats2half2_rn(a, b);
    return *(uint32_t*)&h;
}
__device__ __forceinline__ uint4 ldsm4(uint32_t addr) {
    uint4 r;
    asm volatile("ldmatrix.sync.aligned.m8n8.x4.shared.b16 {%0,%1,%2,%3}, [%4];"
                 : "=r"(r.x), "=r"(r.y), "=r"(r.z), "=r"(r.w) : "r"(addr));
    return r;
}
__device__ __forceinline__ uint4 ldsm4t(uint32_t addr) {
    uint4 r;
    asm volatile("ldmatrix.sync.aligned.m8n8.x4.trans.shared.b16 {%0,%1,%2,%3}, [%4];"
                 : "=r"(r.x), "=r"(r.y), "=r"(r.z), "=r"(r.w) : "r"(addr));
    return r;
}
__device__ __forceinline__ void mma16(float* d, const uint4& a, uint32_t b0, uint32_t b1) {
    asm volatile(
        "mma.sync.aligned.m16n8k16.row.col.f32.f16.f16.f32 "
        "{%0,%1,%2,%3},{%4,%5,%6,%7},{%8,%9},{%0,%1,%2,%3};"
        : "+f"(d[0]), "+f"(d[1]), "+f"(d[2]), "+f"(d[3])
        : "r"(a.x), "r"(a.y), "r"(a.z), "r"(a.w), "r"(b0), "r"(b1));
}
#define CP16(dst, src) \
    asm volatile("cp.async.cg.shared.global [%0], [%1], 16;" :: "r"(dst), "l"(src))
#define CP_COMMIT() asm volatile("cp.async.commit_group;" ::: "memory")
#define CP_WAIT0()  asm volatile("cp.async.wait_group 0;" ::: "memory")

// ================================================================
// fp32 -> fp16 convert (3 tensors per launch, equal sizes)
// ================================================================
__global__ __launch_bounds__(256)
void conv_f2h(const float* __restrict__ s0, const float* __restrict__ s1,
              const float* __restrict__ s2, __half* __restrict__ d0,
              __half* __restrict__ d1, __half* __restrict__ d2)
{
    const float* s = blockIdx.y == 0 ? s0 : (blockIdx.y == 1 ? s1 : s2);
    __half*      d = blockIdx.y == 0 ? d0 : (blockIdx.y == 1 ? d1 : d2);
    int i = (blockIdx.x * 256 + threadIdx.x) * 4;
    float4 v = *(const float4*)(s + i);
    *(uint2*)(d + i) = make_uint2(pack2(v.x, v.y), pack2(v.z, v.w));
}

// ================================================================
// fp16-in GEMM core: C[128,128] = X @ W^T + bias
// BK=32, cp.async double-buffered, 256 threads = 8 warps (2m x 4n)
// smem pitch 40 halves (80B): conflict-free ldmatrix, 16B-aligned cp
// ================================================================
template <bool HOUT>
__device__ __forceinline__ void gemm_core_f16(
    const __half* __restrict__ X, const __half* __restrict__ Wt,
    const float* __restrict__ bias, void* __restrict__ Cv,
    int bm, int bn)
{
    __shared__ __half As[2][128 * 40];
    __shared__ __half Bs[2][128 * 40];

    const int tid = threadIdx.x, lane = tid & 31, wid = tid >> 5;
    const int wm = (wid & 1) * 64, wn = (wid >> 1) * 32;
    const int g = lane >> 2, t = lane & 3;

    float acc[4][4][4];
    #pragma unroll
    for (int mt = 0; mt < 4; mt++)
      #pragma unroll
      for (int nt = 0; nt < 4; nt++)
        #pragma unroll
        for (int i = 0; i < 4; i++) acc[mt][nt][i] = 0.f;

    const uint32_t aB[2] = {smem_u32(As[0]), smem_u32(As[1])};
    const uint32_t bB[2] = {smem_u32(Bs[0]), smem_u32(Bs[1])};

    const int fr = tid >> 1, fc = (tid & 1) * 16;     // fill map
    const __half* xs0 = X  + (size_t)(bm + fr) * DMODEL + fc;
    const __half* ws0 = Wt + (size_t)(bn + fr) * DMODEL + fc;
    const uint32_t adoff = (fr * 40 + fc) * 2;

    // prologue: fill buf0 (kt=0)
    {
        uint32_t ad = aB[0] + adoff, bd = bB[0] + adoff;
        CP16(ad, xs0); CP16(ad + 16, xs0 + 8);
        CP16(bd, ws0); CP16(bd + 16, ws0 + 8);
        CP_COMMIT();
    }

    const uint32_t afroff = ((wm + (lane & 15)) * 40 + (lane >> 4) * 8) * 2;
    const uint32_t bfroff = ((wn + (lane & 15)) * 40 + (lane >> 4) * 8) * 2;

    #pragma unroll 1
    for (int kt = 0; kt < DMODEL / 32; ++kt) {
        CP_WAIT0();
        __syncthreads();
        const int buf = kt & 1;
        if (kt + 1 < DMODEL / 32) {
            const int nb = buf ^ 1;
            uint32_t ad = aB[nb] + adoff, bd = bB[nb] + adoff;
            const __half* xs = xs0 + (kt + 1) * 32;
            const __half* ws = ws0 + (kt + 1) * 32;
            CP16(ad, xs); CP16(ad + 16, xs + 8);
            CP16(bd, ws); CP16(bd + 16, ws + 8);
            CP_COMMIT();
        }
        const uint32_t afr = aB[buf] + afroff;
        const uint32_t bfr = bB[buf] + bfroff;
        #pragma unroll
        for (int ks = 0; ks < 2; ++ks) {
            uint4 b0 = ldsm4(bfr + ks * 32);
            uint4 b1 = ldsm4(bfr + 16 * 80 + ks * 32);
            #pragma unroll
            for (int mt = 0; mt < 4; ++mt) {
                uint4 a = ldsm4(afr + mt * 16 * 80 + ks * 32);
                mma16(acc[mt][0], a, b0.x, b0.z);
                mma16(acc[mt][1], a, b0.y, b0.w);
                mma16(acc[mt][2], a, b1.x, b1.z);
                mma16(acc[mt][3], a, b1.y, b1.w);
            }
        }
        __syncthreads();
    }

    #pragma unroll
    for (int mt = 0; mt < 4; mt++) {
        int r0 = bm + wm + mt * 16 + g;
        #pragma unroll
        for (int nt = 0; nt < 4; nt++) {
            int c = bn + wn + nt * 8 + 2 * t;
            float2 bb = *(const float2*)(bias + c);
            float o00 = acc[mt][nt][0] + bb.x, o01 = acc[mt][nt][1] + bb.y;
            float o10 = acc[mt][nt][2] + bb.x, o11 = acc[mt][nt][3] + bb.y;
            if (HOUT) {
                __half* C = (__half*)Cv;
                *(uint32_t*)(C + (size_t)r0 * DMODEL + c)       = pack2(o00, o01);
                *(uint32_t*)(C + (size_t)(r0 + 8) * DMODEL + c) = pack2(o10, o11);
            } else {
                float* C = (float*)Cv;
                *(float2*)(C + (size_t)r0 * DMODEL + c)       = make_float2(o00, o01);
                *(float2*)(C + (size_t)(r0 + 8) * DMODEL + c) = make_float2(o10, o11);
            }
        }
    }
}

// q and k projections fused (both use Wk)
__global__ __launch_bounds__(256, 2)
void gemm_qk(const __half* __restrict__ xq, const __half* __restrict__ xk,
             const __half* __restrict__ wh, const float* __restrict__ bias,
             __half* __restrict__ qo, __half* __restrict__ ko)
{
    const int sel = blockIdx.y >> 5;
    const int bm = (blockIdx.y & 31) * 128, bn = blockIdx.x * 128;
    gemm_core_f16<true>(sel ? xk : xq, wh, bias, sel ? ko : qo, bm, bn);
}

template <bool HOUT>
__global__ __launch_bounds__(256, 2)
void gemm_one(const __half* __restrict__ X, const __half* __restrict__ wh,
              const float* __restrict__ bias, void* __restrict__ C)
{
    gemm_core_f16<HOUT>(X, wh, bias, C, blockIdx.y * 128, blockIdx.x * 128);
}

// ================================================================
// Fused causal attention + normalization. Block = 128q x 64k tiles.
// 8 warps (4m x 2n), warp 32x32. cp.async staging, dbuf K/V.
// Tail: rescale own w rows (replaces norm_w kernel).
// ================================================================
#define SK0 9216
#define SK1 13824
#define SV0 18432
#define SV1 23040
#define SP  27648
#define ATTN_SMEM (73728 + 256 * 4)

__global__ __launch_bounds__(256, 2)
void attn_h(const __half* __restrict__ qp, const __half* __restrict__ kp,
            const __half* __restrict__ vp, float* __restrict__ w,
            __half* __restrict__ ctx)
{
    extern __shared__ __half hs[];
    float* rsum_sm = (float*)(hs + 36864);
    float* invsm   = rsum_sm + 128;

    const int qt = 15 - (int)blockIdx.x;      // big tiles first
    const int h = blockIdx.y, b = blockIdx.z;
    const int q0 = qt * 128;
    const int nkt = 2 * qt + 2;
    const int tid = threadIdx.x, lane = tid & 31, wid = tid >> 5;
    const int wm = (wid & 3) * 32, wn = (wid >> 2) * 32;
    const int g = lane >> 2, t = lane & 3;
    const uint32_t sb = smem_u32(hs);

    if (tid < 128) rsum_sm[tid] = 0.f;

    const uint32_t qfr = sb + (((wm + (lane & 15)) * 72 + (lane >> 4) * 8) << 1);
    const uint32_t pfr = sb + ((SP + (wm + (lane & 15)) * 72 + (lane >> 4) * 8) << 1);
    const uint32_t kfroff = (((wn + (lane & 15)) * 72 + (lane >> 4) * 8) << 1);
    const uint32_t vfroff = (((lane & 15) * 72 + wn + (lane >> 4) * 8) << 1);

    const int qr = tid >> 1, qc = (tid & 1) * 32;
    const int kr = tid >> 2, kc = (tid & 3) * 16;
    const __half* ksrc0 = kp + (size_t)(b * SEQ + kr) * DMODEL + h * HDIM + kc;
    const __half* vsrc0 = vp + (size_t)(b * SEQ + kr) * DMODEL + h * HDIM + kc;

    {
        uint32_t qd = sb + ((qr * 72 + qc) << 1);
        const __half* qs = qp + (size_t)(b * SEQ + q0 + qr) * DMODEL + h * HDIM + qc;
        CP16(qd, qs); CP16(qd + 16, qs + 8); CP16(qd + 32, qs + 16); CP16(qd + 48, qs + 24);
        uint32_t kd = sb + ((SK0 + kr * 72 + kc) << 1);
        uint32_t vd = sb + ((SV0 + kr * 72 + kc) << 1);
        CP16(kd, ksrc0); CP16(kd + 16, ksrc0 + 8);
        CP16(vd, vsrc0); CP16(vd + 16, vsrc0 + 8);
        CP_COMMIT();
    }

    float cacc[2][4][4];
    #pragma unroll
    for (int m = 0; m < 2; m++)
      #pragma unroll
      for (int nt = 0; nt < 4; nt++)
        #pragma unroll
        for (int i = 0; i < 4; i++) cacc[m][nt][i] = 0.f;
    float rs[2][2] = {{0.f, 0.f}, {0.f, 0.f}};

    float* wbase = w + (size_t)((b * NHEADS + h) * SEQ) * SEQ;

    for (int kt = 0; kt < nkt; ++kt) {
        CP_WAIT0();
        __syncthreads();
        const int buf = kt & 1;

        if (kt + 1 < nkt) {
            const int nb = buf ^ 1;
            uint32_t kd = sb + (((nb ? SK1 : SK0) + kr * 72 + kc) << 1);
            uint32_t vd = sb + (((nb ? SV1 : SV0) + kr * 72 + kc) << 1);
            const __half* ks = ksrc0 + (size_t)(kt + 1) * 64 * DMODEL;
            const __half* vs = vsrc0 + (size_t)(kt + 1) * 64 * DMODEL;
            CP16(kd, ks); CP16(kd + 16, ks + 8);
            CP16(vd, vs); CP16(vd + 16, vs + 8);
            CP_COMMIT();
        }

        const uint32_t kfr = sb + (((buf ? SK1 : SK0)) << 1) + kfroff;
        const uint32_t vfr = sb + (((buf ? SV1 : SV0)) << 1) + vfroff;

        // GEMM1: S = Q K^T
        float s[2][4][4];
        #pragma unroll
        for (int m = 0; m < 2; m++)
          #pragma unroll
          for (int nt = 0; nt < 4; nt++)
            #pragma unroll
            for (int i = 0; i < 4; i++) s[m][nt][i] = 0.f;
        #pragma unroll
        for (int kd = 0; kd < 64; kd += 16) {
            uint4 a0 = ldsm4(qfr + (kd << 1));
            uint4 a1 = ldsm4(qfr + ((16 * 72 + kd) << 1));
            #pragma unroll
            for (int nb = 0; nb < 2; ++nb) {
                uint4 bf = ldsm4(kfr + ((nb * 16 * 72 + kd) << 1));
                mma16(s[0][nb * 2],     a0, bf.x, bf.z);
                mma16(s[0][nb * 2 + 1], a0, bf.y, bf.w);
                mma16(s[1][nb * 2],     a1, bf.x, bf.z);
                mma16(s[1][nb * 2 + 1], a1, bf.y, bf.w);
            }
        }

        // exp, mask, write unnormalized w, rowsums, stage P
        const int k0 = kt * 64;
        #pragma unroll
        for (int m = 0; m < 2; m++) {
            const int r0g = q0 + wm + m * 16 + g, r1g = r0g + 8;
            #pragma unroll
            for (int nt = 0; nt < 4; nt++) {
                int ck = k0 + wn + nt * 8 + 2 * t;
                float e00 = __expf(s[m][nt][0] * 0.125f); if (ck     > r0g) e00 = 0.f;
                float e01 = __expf(s[m][nt][1] * 0.125f); if (ck + 1 > r0g) e01 = 0.f;
                float e10 = __expf(s[m][nt][2] * 0.125f); if (ck     > r1g) e10 = 0.f;
                float e11 = __expf(s[m][nt][3] * 0.125f); if (ck + 1 > r1g) e11 = 0.f;
                rs[m][0] += e00 + e01;
                rs[m][1] += e10 + e11;
                *(float2*)(wbase + (size_t)r0g * SEQ + ck) = make_float2(e00, e01);
                *(float2*)(wbase + (size_t)r1g * SEQ + ck) = make_float2(e10, e11);
                int pc = wn + nt * 8 + 2 * t;
                *(uint32_t*)(hs + SP + (wm + m * 16 + g) * 72 + pc)     = pack2(e00, e01);
                *(uint32_t*)(hs + SP + (wm + m * 16 + g + 8) * 72 + pc) = pack2(e10, e11);
            }
        }
        __syncthreads();

        // GEMM2: ctx += P V
        #pragma unroll
        for (int kk = 0; kk < 64; kk += 16) {
            uint4 a0 = ldsm4(pfr + (kk << 1));
            uint4 a1 = ldsm4(pfr + ((16 * 72 + kk) << 1));
            #pragma unroll
            for (int nb = 0; nb < 2; ++nb) {
                uint4 bf = ldsm4t(vfr + ((kk * 72 + nb * 16) << 1));
                mma16(cacc[0][nb * 2],     a0, bf.x, bf.y);
                mma16(cacc[0][nb * 2 + 1], a0, bf.z, bf.w);
                mma16(cacc[1][nb * 2],     a1, bf.x, bf.y);
                mma16(cacc[1][nb * 2 + 1], a1, bf.z, bf.w);
            }
        }
    }

    // rowsum reduce -> invsm
    #pragma unroll
    for (int m = 0; m < 2; m++)
      #pragma unroll
      for (int hf = 0; hf < 2; hf++) {
          rs[m][hf] += __shfl_xor_sync(0xffffffffu, rs[m][hf], 1);
          rs[m][hf] += __shfl_xor_sync(0xffffffffu, rs[m][hf], 2);
      }
    if (t == 0) {
        atomicAdd(&rsum_sm[wm + g],          rs[0][0]);
        atomicAdd(&rsum_sm[wm + g + 8],      rs[0][1]);
        atomicAdd(&rsum_sm[wm + 16 + g],     rs[1][0]);
        atomicAdd(&rsum_sm[wm + 16 + g + 8], rs[1][1]);
    }
    __syncthreads();
    if (tid < 128) invsm[tid] = 1.0f / rsum_sm[tid];
    __syncthreads();

    // store normalized ctx (fp16) in concat layout [b, s, h*64+d]
    #pragma unroll
    for (int m = 0; m < 2; m++) {
        float iv0 = invsm[wm + m * 16 + g], iv1 = invsm[wm + m * 16 + g + 8];
        int r0 = q0 + wm + m * 16 + g;
        #pragma unroll
        for (int nt = 0; nt < 4; nt++) {
            int c = h * HDIM + wn + nt * 8 + 2 * t;
            *(uint32_t*)(ctx + (size_t)(b * SEQ + r0) * DMODEL + c) =
                pack2(cacc[m][nt][0] * iv0, cacc[m][nt][1] * iv0);
            *(uint32_t*)(ctx + (size_t)(b * SEQ + r0 + 8) * DMODEL + c) =
                pack2(cacc[m][nt][2] * iv1, cacc[m][nt][3] * iv1);
        }
    }

    // tail 1: zero-fill masked tiles of w
    {
        const int tcol = tid & 15, trow = tid >> 4;
        for (int kt2 = nkt; kt2 < NQT; ++kt2) {
            int k0 = kt2 * 64;
            #pragma unroll
            for (int rr = 0; rr < 8; ++rr) {
                int row = q0 + trow + rr * 16;
                *(float4*)(wbase + (size_t)row * SEQ + k0 + tcol * 4) =
                    make_float4(0.f, 0.f, 0.f, 0.f);
            }
        }
        // tail 2: normalize own w rows (replaces norm_w kernel)
        for (int kt2 = 0; kt2 < nkt; ++kt2) {
            int k0 = kt2 * 64;
            #pragma unroll
            for (int rr = 0; rr < 8; ++rr) {
                int row = trow + rr * 16;
                float iv = invsm[row];
                float4* p = (float4*)(wbase + (size_t)(q0 + row) * SEQ + k0 + tcol * 4);
                float4 v = *p;
                v.x *= iv; v.y *= iv; v.z *= iv; v.w *= iv;
                *p = v;
            }
        }
    }
}

// ================================================================
// launch
// ================================================================
extern "C" void kernel_launch(void* const* d_in, const int* in_sizes, int n_in,
                              void* d_out, int out_size)
{
    const float* query = (const float*)d_in[0];
    const float* key   = (const float*)d_in[1];
    const float* value = (const float*)d_in[2];
    const float* Wk = (const float*)d_in[4];
    const float* bk = (const float*)d_in[5];
    const float* Wv = (const float*)d_in[6];
    const float* bv = (const float*)d_in[7];
    const float* Wo = (const float*)d_in[8];
    const float* bo = (const float*)d_in[9];

    float* out = (float*)d_out;
    float* w   = out + (size_t)BATCH * SEQ * DMODEL;

    __half *xq, *xk, *xv, *whk, *whv, *who, *qp, *kp, *vp, *ctx;
    cudaGetSymbolAddress((void**)&xq,  g_xq);
    cudaGetSymbolAddress((void**)&xk,  g_xk);
    cudaGetSymbolAddress((void**)&xv,  g_xv);
    cudaGetSymbolAddress((void**)&whk, g_whk);
    cudaGetSymbolAddress((void**)&whv, g_whv);
    cudaGetSymbolAddress((void**)&who, g_who);
    cudaGetSymbolAddress((void**)&qp,  g_qp);
    cudaGetSymbolAddress((void**)&kp,  g_kp);
    cudaGetSymbolAddress((void**)&vp,  g_vp);
    cudaGetSymbolAddress((void**)&ctx, g_ctx);

    cudaFuncSetAttribute(attn_h,
                         cudaFuncAttributeMaxDynamicSharedMemorySize,
                         ATTN_SMEM);

    // fp32 -> fp16 conversions
    conv_f2h<<<dim3((BATCH * SEQ * DMODEL) / 1024, 3), 256>>>(
        query, key, value, xq, xk, xv);
    conv_f2h<<<dim3((DMODEL * DMODEL) / 1024, 3), 256>>>(
        Wk, Wv, Wo, whk, whv, who);

    // projections (ref bug: q uses Wk)
    gemm_qk<<<dim3(8, 64), 256>>>(xq, xk, whk, bk, qp, kp);
    gemm_one<true><<<dim3(8, 32), 256>>>(xv, whv, bv, vp);

    // fused attention + softmax-normalize (writes w and fp16 ctx)
    attn_h<<<dim3(16, NHEADS, BATCH), 256, ATTN_SMEM>>>(qp, kp, vp, w, ctx);

    // output projection (fp32 out)
    gemm_one<false><<<dim3(8, 32), 256>>>(ctx, who, bo, out);
}